// round 14
// baseline (speedup 1.0000x reference)
#include <cuda_runtime.h>
#include <cstdint>
#include <cstddef>

#define NN   100000
#define EE   1600000
#define DDIM 128
#define RREL 8
#define BBAS 4
#define OUTD 64

// ---------------- scratch (no cudaMalloc allowed) ----------------
__device__ float g_Z[(size_t)NN * 512];     // contracted aggregate [N, B*D]
__device__ float g_tau[(size_t)NN * DDIM];  // gate tau [N, D]
__device__ int   g_sd[EE];                  // edges sorted by dst: src | (q<<20)
__device__ int   g_ss[EE];                  // edges sorted by src: dst
__device__ int   g_offd[NN + 1];
__device__ int   g_offs[NN + 1];
__device__ int   g_curd[NN];
__device__ int   g_curs[NN];
__device__ int   g_cntq[NN * RREL];         // per-(dst,rel) edge counts
__device__ int   g_part[2 * 128];           // scan partials
// interleaved tf32 (hi,lo) weights: proj | basis1,root1 | basis2,root2 | outW
__device__ float g_Wi[2 * 188416];

#define WOFF_PROJ 0
#define WOFF_B1   16384
#define WOFF_R1   81920
#define WOFF_B2   98304
#define WOFF_R2   163840
#define WOFF_OUT  180224

// ---------------- tf32 split helpers ----------------
__device__ __forceinline__ void split_tf32(float x, uint32_t& hi, uint32_t& lo) {
    uint32_t xb = __float_as_uint(x) & 0xFFFFE000u;
    hi = xb;
    float l = x - __uint_as_float(xb);
    asm("cvt.rna.tf32.f32 %0, %1;" : "=r"(lo) : "f"(l));
}
__device__ __forceinline__ void mma8(float* d, const uint32_t* a, uint32_t b0, uint32_t b1) {
    asm volatile(
        "mma.sync.aligned.m16n8k8.row.col.f32.tf32.tf32.f32 "
        "{%0,%1,%2,%3}, {%4,%5,%6,%7}, {%8,%9}, {%0,%1,%2,%3};"
        : "+f"(d[0]), "+f"(d[1]), "+f"(d[2]), "+f"(d[3])
        : "r"(a[0]), "r"(a[1]), "r"(a[2]), "r"(a[3]), "r"(b0), "r"(b1));
}

// ---------------- cp.async helpers ----------------
__device__ __forceinline__ void cp16(uint32_t dst, const void* src, int srcsz) {
    asm volatile("cp.async.ca.shared.global [%0], [%1], 16, %2;"
                 :: "r"(dst), "l"(src), "r"(srcsz));
}
__device__ __forceinline__ void cp_commit() {
    asm volatile("cp.async.commit_group;");
}
template <int N>
__device__ __forceinline__ void cp_wait() {
    asm volatile("cp.async.wait_group %0;" :: "n"(N));
}

// ---------------- merged weight pre-split (6 matrices, one launch) ----------------
__global__ void splitW6_k(const float* W0, const float* W1, const float* W2,
                          const float* W3, const float* W4, const float* W5,
                          float* __restrict__ Wi) {
    int i = blockIdx.x * 256 + threadIdx.x;   // global element id, total 188416
    if (i >= 188416) return;
    const float* W; int local;
    if (i < 16384)        { W = W0; local = i; }
    else if (i < 81920)   { W = W1; local = i - 16384; }
    else if (i < 98304)   { W = W2; local = i - 81920; }
    else if (i < 163840)  { W = W3; local = i - 98304; }
    else if (i < 180224)  { W = W4; local = i - 163840; }
    else                  { W = W5; local = i - 180224; }
    uint32_t hi, lo;
    split_tf32(W[local], hi, lo);
    Wi[2 * i]     = __uint_as_float(hi);
    Wi[2 * i + 1] = __uint_as_float(lo);
}

// ---------------- sorting: histogram / 3-phase scan / scatter ----------------
__global__ void hist_k(const int* __restrict__ src, const int* __restrict__ dst,
                       const int* __restrict__ et,
                       int* __restrict__ hs, int* __restrict__ hd,
                       int* __restrict__ cq) {
    int e = blockIdx.x * 256 + threadIdx.x;
    if (e < EE) {
        int t = dst[e];
        atomicAdd(&hd[t], 1);
        atomicAdd(&hs[src[e]], 1);
        atomicAdd(&cq[t * RREL + et[e]], 1);
    }
}

// phase 1: per-block exclusive scan of 1024-chunk; partial = block total
__global__ void scan1_k(const int* __restrict__ h0, int* __restrict__ o0,
                        const int* __restrict__ h1, int* __restrict__ o1,
                        int* __restrict__ part) {
    int seg = blockIdx.y;
    const int* hist = seg ? h1 : h0;
    int* off        = seg ? o1 : o0;
    __shared__ int buf[2][1024];
    int t = threadIdx.x;
    int base = blockIdx.x * 1024;
    int v = (base + t < NN) ? hist[base + t] : 0;
    buf[0][t] = v;
    __syncthreads();
    int pi = 0;
#pragma unroll
    for (int ofs = 1; ofs < 1024; ofs <<= 1) {
        int x = buf[pi][t];
        if (t >= ofs) x += buf[pi][t - ofs];
        buf[pi ^ 1][t] = x;
        pi ^= 1;
        __syncthreads();
    }
    int incl = buf[pi][t];
    if (base + t < NN) off[base + t] = incl - v;      // block-local exclusive
    if (t == 1023) part[seg * 128 + blockIdx.x] = incl;
}

// phase 2: exclusive scan of the 98 partials per segment (one block, 256 thr)
__global__ void scan2_k(int* __restrict__ part) {
    __shared__ int b[2][2][128];
    int t = threadIdx.x;          // 0..255
    int seg = t >> 7, i = t & 127;
    int v = (i < 98) ? part[seg * 128 + i] : 0;
    b[0][seg][i] = v;
    __syncthreads();
    int pi = 0;
#pragma unroll
    for (int ofs = 1; ofs < 128; ofs <<= 1) {
        int x = b[pi][seg][i];
        if (i >= ofs) x += b[pi][seg][i - ofs];
        b[pi ^ 1][seg][i] = x;
        pi ^= 1;
        __syncthreads();
    }
    part[seg * 128 + i] = b[pi][seg][i] - v;          // exclusive
}

// phase 3: add partials, mirror into cur arrays. Total is EE by construction.
__global__ void scan3_k(int* __restrict__ o0, int* __restrict__ c0,
                        int* __restrict__ o1, int* __restrict__ c1,
                        const int* __restrict__ part) {
    int seg = blockIdx.y;
    int* off = seg ? o1 : o0;
    int* cur = seg ? c1 : c0;
    int i = blockIdx.x * 1024 + threadIdx.x;
    if (i < NN) {
        int o = off[i] + part[seg * 128 + blockIdx.x];
        off[i] = o;
        cur[i] = o;
    }
    if (i == 0) off[NN] = EE;
}

__global__ void scatter_k(const int* __restrict__ src, const int* __restrict__ dst,
                          const int* __restrict__ et,
                          int* __restrict__ curd, int* __restrict__ curs,
                          int* __restrict__ sd, int* __restrict__ ss) {
    int e = blockIdx.x * 256 + threadIdx.x;
    if (e < EE) {
        int s = src[e], t = dst[e], q = et[e];
        int p = atomicAdd(&curd[t], 1);
        sd[p] = s | (q << 20);
        int p2 = atomicAdd(&curs[s], 1);
        ss[p2] = t;
    }
}

// ---------------- passA: register-accumulated fused mean+contraction -> Z ----------------
__global__ __launch_bounds__(128)
void passA_k(const float* __restrict__ h, const float* __restrict__ comp,
             const int* __restrict__ offd, const int* __restrict__ sd,
             const int* __restrict__ cntq, float* __restrict__ Z) {
    int t = blockIdx.x;
    int d = threadIdx.x;
    __shared__ float scoef[RREL * BBAS];   // [q][b], 16B-aligned per q
    __shared__ int   sed[128];
    if (d < RREL * BBAS) {
        int q = d >> 2;
        float w = 1.0f / fmaxf((float)cntq[t * RREL + q], 1.0f);
        scoef[d] = comp[d] * w;
    }
    __syncthreads();

    float a0 = 0.f, a1 = 0.f, a2 = 0.f, a3 = 0.f;
    int e0 = offd[t], e1 = offd[t + 1];
    for (int base = e0; base < e1; base += 128) {
        int m = min(128, e1 - base);
        if (d < m) sed[d] = sd[base + d];
        __syncthreads();
        int i = 0;
        for (; i + 3 < m; i += 4) {
            int v0 = sed[i], v1 = sed[i + 1], v2 = sed[i + 2], v3 = sed[i + 3];
            float h0 = h[(size_t)(v0 & 0xFFFFF) * DDIM + d];
            float h1 = h[(size_t)(v1 & 0xFFFFF) * DDIM + d];
            float h2 = h[(size_t)(v2 & 0xFFFFF) * DDIM + d];
            float h3 = h[(size_t)(v3 & 0xFFFFF) * DDIM + d];
            float4 c0 = *(const float4*)(&scoef[(v0 >> 20) * 4]);
            float4 c1 = *(const float4*)(&scoef[(v1 >> 20) * 4]);
            float4 c2 = *(const float4*)(&scoef[(v2 >> 20) * 4]);
            float4 c3 = *(const float4*)(&scoef[(v3 >> 20) * 4]);
            a0 += c0.x * h0 + c1.x * h1 + c2.x * h2 + c3.x * h3;
            a1 += c0.y * h0 + c1.y * h1 + c2.y * h2 + c3.y * h3;
            a2 += c0.z * h0 + c1.z * h1 + c2.z * h2 + c3.z * h3;
            a3 += c0.w * h0 + c1.w * h1 + c2.w * h2 + c3.w * h3;
        }
        for (; i < m; ++i) {
            int v = sed[i];
            float hv = h[(size_t)(v & 0xFFFFF) * DDIM + d];
            float4 c = *(const float4*)(&scoef[(v >> 20) * 4]);
            a0 += c.x * hv;
            a1 += c.y * hv;
            a2 += c.z * hv;
            a3 += c.w * hv;
        }
        __syncthreads();
    }

    float* zr = Z + (size_t)t * 512;
    zr[0 * DDIM + d] = a0;
    zr[1 * DDIM + d] = a1;
    zr[2 * DDIM + d] = a2;
    zr[3 * DDIM + d] = a3;
}

// ---------------- passB: per-src gate tau = tanh(mean |h_s - h_d|^2) ----------------
__global__ __launch_bounds__(128)
void passB_k(const float* __restrict__ h, const int* __restrict__ offs,
             const int* __restrict__ ss, float* __restrict__ tau) {
    int s = blockIdx.x;
    int d = threadIdx.x;
    int e0 = offs[s], e1 = offs[s + 1];
    float hs = h[(size_t)s * DDIM + d];
    float a0 = 0.f, a1 = 0.f, a2 = 0.f, a3 = 0.f;
    __shared__ int sed[128];
    for (int base = e0; base < e1; base += 128) {
        int m = min(128, e1 - base);
        if (d < m) sed[d] = ss[base + d];
        __syncthreads();
        int i = 0;
        for (; i + 3 < m; i += 4) {
            float v0 = h[(size_t)sed[i + 0] * DDIM + d];
            float v1 = h[(size_t)sed[i + 1] * DDIM + d];
            float v2 = h[(size_t)sed[i + 2] * DDIM + d];
            float v3 = h[(size_t)sed[i + 3] * DDIM + d];
            float d0 = hs - v0, d1 = hs - v1, d2 = hs - v2, d3 = hs - v3;
            a0 += d0 * d0; a1 += d1 * d1; a2 += d2 * d2; a3 += d3 * d3;
        }
        for (; i < m; ++i) {
            float v = h[(size_t)sed[i] * DDIM + d];
            float df = hs - v;
            a0 += df * df;
        }
        __syncthreads();
    }
    float acc = (a0 + a1) + (a2 + a3);
    float ig = 1.0f / fmaxf((float)(e1 - e0), 1.0f);
    tau[(size_t)s * DDIM + d] = tanhf(acc * ig);
}

// ---------------- 3xTF32 MMA GEMM, cp.async double-buffered, BM=128, BK=16 ----------------
// C[M,NC] = epi( A[M,K] @ W ), A split at col K1A (A1/A2); W interleaved (hi,lo) [K][2*NC]
// 256 threads, warps 4x2: wm=warp&3 (32 rows), wn=warp>>2 (NC/2 cols).
template <int NC, int EPI>
__global__ __launch_bounds__(256)
void gemm_mma(const float* __restrict__ A1, int lda1, int K1A,
              const float* __restrict__ A2, int lda2,
              int M, int K,
              const float* __restrict__ Wi,
              const float* __restrict__ bias,
              const float* __restrict__ hprev,
              const float* __restrict__ tau,
              float* __restrict__ out) {
    constexpr int NCH   = NC / 2;         // cols per warp
    constexpr int NT    = NCH / 8;        // n8 tiles per warp
    constexpr int APAD  = 20;             // 16 + 4
    constexpr int BPAD2 = 2 * NC + 8;     // interleaved row stride
    constexpr int ABUF  = 128 * APAD;     // floats per A buffer
    constexpr int BBUF  = 16 * BPAD2;     // floats per B buffer
    extern __shared__ float sm[];
    float* Asb = sm;                      // [2][128][APAD]
    float* Bsb = sm + 2 * ABUF;           // [2][16][BPAD2]

    const int tid  = threadIdx.x;
    const int lane = tid & 31;
    const int warp = tid >> 5;
    const int wm   = warp & 3;
    const int wn   = warp >> 2;
    const int g    = lane >> 2;
    const int tig  = lane & 3;
    const int row0 = blockIdx.x * 128;

    float acc[2][NT][4];
#pragma unroll
    for (int mt = 0; mt < 2; ++mt)
#pragma unroll
        for (int nt = 0; nt < NT; ++nt)
#pragma unroll
            for (int j = 0; j < 4; ++j) acc[mt][nt][j] = 0.f;

    const int nch = K >> 4;

    auto load_chunk = [&](int c, int buf) {
        const int k0g = c << 4;
        const float* Ap; int lda;
        if (k0g < K1A) { Ap = A1 + k0g; lda = lda1; }
        else           { Ap = A2 + (k0g - K1A); lda = lda2; }
        float* As = Asb + buf * ABUF;
        // A: 128 rows x 4 float4 = 512 slots, 2/thread
#pragma unroll
        for (int u = 0; u < 2; ++u) {
            int f = u * 256 + tid;
            int r = f >> 2;
            int q = f & 3;
            int grow = row0 + r;
            uint32_t dsts = (uint32_t)__cvta_generic_to_shared(As + r * APAD + q * 4);
            const float* srcp = Ap + (size_t)(grow < M ? grow : 0) * lda + q * 4;
            cp16(dsts, srcp, grow < M ? 16 : 0);
        }
        // B: 16 rows x (NC/2) float4 = 16*NC/2 slots, NC/32 per thread
        float* Bsl = Bsb + buf * BBUF;
        const float* Wp = Wi + (size_t)k0g * (2 * NC);
#pragma unroll
        for (int u = 0; u < NC / 32; ++u) {
            int f = u * 256 + tid;
            int r = f / (NC / 2);
            int c4 = f % (NC / 2);
            uint32_t dsts = (uint32_t)__cvta_generic_to_shared(Bsl + r * BPAD2 + c4 * 4);
            cp16(dsts, Wp + (size_t)r * 2 * NC + c4 * 4, 16);
        }
    };

    load_chunk(0, 0);
    cp_commit();

    for (int c = 0; c < nch; ++c) {
        const int buf = c & 1;
        if (c + 1 < nch) {
            load_chunk(c + 1, buf ^ 1);
            cp_commit();
            cp_wait<1>();
        } else {
            cp_wait<0>();
        }
        __syncthreads();

        const float* As = Asb + buf * ABUF;
        const float* Bs = Bsb + buf * BBUF;
#pragma unroll
        for (int k8 = 0; k8 < 2; ++k8) {
            const int k0 = k8 * 8;
            uint32_t ah[2][4], al[2][4];
#pragma unroll
            for (int mt = 0; mt < 2; ++mt) {
                int rb = wm * 32 + mt * 16 + g;
                split_tf32(As[rb * APAD + k0 + tig],           ah[mt][0], al[mt][0]);
                split_tf32(As[(rb + 8) * APAD + k0 + tig],     ah[mt][1], al[mt][1]);
                split_tf32(As[rb * APAD + k0 + tig + 4],       ah[mt][2], al[mt][2]);
                split_tf32(As[(rb + 8) * APAD + k0 + tig + 4], ah[mt][3], al[mt][3]);
            }
#pragma unroll
            for (int nt = 0; nt < NT; ++nt) {
                int cb = wn * NCH + nt * 8 + g;
                float2 p0 = *(const float2*)(Bs + (k0 + tig) * BPAD2 + 2 * cb);
                float2 p1 = *(const float2*)(Bs + (k0 + tig + 4) * BPAD2 + 2 * cb);
                uint32_t bh0 = __float_as_uint(p0.x), bl0 = __float_as_uint(p0.y);
                uint32_t bh1 = __float_as_uint(p1.x), bl1 = __float_as_uint(p1.y);
#pragma unroll
                for (int mt = 0; mt < 2; ++mt) {
                    mma8(acc[mt][nt], ah[mt], bh0, bh1);
                    mma8(acc[mt][nt], al[mt], bh0, bh1);
                    mma8(acc[mt][nt], ah[mt], bl0, bl1);
                }
            }
        }
        __syncthreads();
    }

    // ---- epilogue ----
#pragma unroll
    for (int mt = 0; mt < 2; ++mt) {
#pragma unroll
        for (int nt = 0; nt < NT; ++nt) {
            int col = wn * NCH + nt * 8 + 2 * tig;
            int r0 = row0 + wm * 32 + mt * 16 + g;
#pragma unroll
            for (int half = 0; half < 2; ++half) {
                int row = r0 + half * 8;
                if (row >= M) continue;
                float c0 = acc[mt][nt][half * 2 + 0];
                float c1 = acc[mt][nt][half * 2 + 1];
                if (EPI == 0) {
                    c0 = fmaxf(c0 + bias[col], 0.f);
                    c1 = fmaxf(c1 + bias[col + 1], 0.f);
                } else if (EPI == 1) {
                    float hn0 = fmaxf(c0 + bias[col], 0.f);
                    float hn1 = fmaxf(c1 + bias[col + 1], 0.f);
                    float hp0 = hprev[(size_t)row * DDIM + col];
                    float hp1 = hprev[(size_t)row * DDIM + col + 1];
                    float t0 = tau[(size_t)row * DDIM + col];
                    float t1 = tau[(size_t)row * DDIM + col + 1];
                    c0 = hp0 + t0 * (hn0 - hp0);
                    c1 = hp1 + t1 * (hn1 - hp1);
                } else {
                    c0 += bias[col];
                    c1 += bias[col + 1];
                }
                *(float2*)(out + (size_t)row * NC + col) = make_float2(c0, c1);
            }
        }
    }
}

// ---------------- launch ----------------
extern "C" void kernel_launch(void* const* d_in, const int* in_sizes, int n_in,
                              void* d_out, int out_size) {
    (void)in_sizes; (void)n_in; (void)out_size;
    const float* x      = (const float*)d_in[0];
    const int*   src    = (const int*)d_in[1];
    const int*   dst    = (const int*)d_in[2];
    const int*   et     = (const int*)d_in[3];
    const float* projW  = (const float*)d_in[4];
    const float* projb  = (const float*)d_in[5];
    const float* basis1 = (const float*)d_in[6];
    const float* comp1  = (const float*)d_in[7];
    const float* root1  = (const float*)d_in[8];
    const float* bias1  = (const float*)d_in[9];
    const float* basis2 = (const float*)d_in[10];
    const float* comp2  = (const float*)d_in[11];
    const float* root2  = (const float*)d_in[12];
    const float* bias2  = (const float*)d_in[13];
    const float* outW   = (const float*)d_in[14];
    const float* outb   = (const float*)d_in[15];

    float* o  = (float*)d_out;
    float* L0 = o + (size_t)NN * OUTD;        // latents[0]
    float* L1 = L0 + (size_t)NN * DDIM;       // latents[1]
    float* L2 = L1 + (size_t)NN * DDIM;       // latents[2]

    float *Z, *tau, *Wi;
    int *sd, *ss, *offd, *offs, *curd, *curs, *cntq, *part;
    cudaGetSymbolAddress((void**)&Z,    g_Z);
    cudaGetSymbolAddress((void**)&tau,  g_tau);
    cudaGetSymbolAddress((void**)&Wi,   g_Wi);
    cudaGetSymbolAddress((void**)&sd,   g_sd);
    cudaGetSymbolAddress((void**)&ss,   g_ss);
    cudaGetSymbolAddress((void**)&offd, g_offd);
    cudaGetSymbolAddress((void**)&offs, g_offs);
    cudaGetSymbolAddress((void**)&curd, g_curd);
    cudaGetSymbolAddress((void**)&curs, g_curs);
    cudaGetSymbolAddress((void**)&cntq, g_cntq);
    cudaGetSymbolAddress((void**)&part, g_part);

    const int gblocks = (NN + 127) / 128;     // 782
    const int eblocks = (EE + 255) / 256;
    const int nblk1k  = (NN + 1023) / 1024;   // 98

    const int SMEM128 = (2 * 128 * 20 + 2 * 16 * 264) * 4;   // 54272
    const int SMEM64  = (2 * 128 * 20 + 2 * 16 * 136) * 4;   // 37888
    cudaFuncSetAttribute(gemm_mma<128, 0>, cudaFuncAttributeMaxDynamicSharedMemorySize, SMEM128);
    cudaFuncSetAttribute(gemm_mma<128, 1>, cudaFuncAttributeMaxDynamicSharedMemorySize, SMEM128);
    cudaFuncSetAttribute(gemm_mma<64, 2>,  cudaFuncAttributeMaxDynamicSharedMemorySize, SMEM64);

    // ---- pre-split weights (layer-invariant, one launch) ----
    splitW6_k<<<(188416 + 255) / 256, 256>>>(projW, basis1, root1, basis2, root2, outW, Wi);

    // ---- build CSR + per-(dst,rel) counts (layer-invariant) ----
    cudaMemsetAsync(curd, 0, NN * sizeof(int));
    cudaMemsetAsync(curs, 0, NN * sizeof(int));
    cudaMemsetAsync(cntq, 0, NN * RREL * sizeof(int));
    hist_k<<<eblocks, 256>>>(src, dst, et, curs, curd, cntq);
    scan1_k<<<dim3(nblk1k, 2), 1024>>>(curd, offd, curs, offs, part);
    scan2_k<<<1, 256>>>(part);
    scan3_k<<<dim3(nblk1k, 2), 1024>>>(offd, curd, offs, curs, part);
    scatter_k<<<eblocks, 256>>>(src, dst, et, curd, curs, sd, ss);

    // ---- input projection: h0 = relu(x @ projW + projb) ----
    gemm_mma<128, 0><<<gblocks, 256, SMEM128>>>(x, 128, 128, x, 128, NN, 128,
                                                Wi + 2 * WOFF_PROJ,
                                                projb, nullptr, nullptr, L0);

    // ---- layer 1 ----
    passA_k<<<NN, 128>>>(L0, comp1, offd, sd, cntq, Z);
    passB_k<<<NN, 128>>>(L0, offs, ss, tau);
    gemm_mma<128, 1><<<gblocks, 256, SMEM128>>>(Z, 512, 512, L0, 128, NN, 640,
                                                Wi + 2 * WOFF_B1,
                                                bias1, L0, tau, L1);

    // ---- layer 2 ----
    passA_k<<<NN, 128>>>(L1, comp2, offd, sd, cntq, Z);
    passB_k<<<NN, 128>>>(L1, offs, ss, tau);
    gemm_mma<128, 1><<<gblocks, 256, SMEM128>>>(Z, 512, 512, L1, 128, NN, 640,
                                                Wi + 2 * WOFF_B2,
                                                bias2, L1, tau, L2);

    // ---- final: out = h2 @ outW + outb ----
    gemm_mma<64, 2><<<gblocks, 256, SMEM64>>>(L2, 128, 128, L2, 128, NN, 128,
                                              Wi + 2 * WOFF_OUT,
                                              outb, nullptr, nullptr, o);
}

// round 15
// speedup vs baseline: 1.1352x; 1.1352x over previous
#include <cuda_runtime.h>
#include <cstdint>
#include <cstddef>

#define NN   100000
#define EE   1600000
#define DDIM 128
#define RREL 8
#define BBAS 4
#define OUTD 64

// ---------------- scratch (no cudaMalloc allowed) ----------------
__device__ float g_Z[(size_t)NN * 512];     // contracted aggregate [N, B*D]
__device__ float g_tau[(size_t)NN * DDIM];  // gate tau [N, D]
__device__ int   g_sd[EE];                  // edges sorted by dst: src | (q<<20)
__device__ int   g_ss[EE];                  // edges sorted by src: dst
__device__ int   g_offd[NN + 1];
__device__ int   g_offs[NN + 1];
__device__ int   g_curd[NN];
__device__ int   g_curs[NN];
__device__ int   g_cntq[NN * RREL];         // per-(dst,rel) edge counts
__device__ int   g_part[2 * 128];           // scan partials
// interleaved tf32 (hi,lo) weights: proj | basis1,root1 | basis2,root2 | outW
__device__ float g_Wi[2 * 188416];

#define WOFF_PROJ 0
#define WOFF_B1   16384
#define WOFF_R1   81920
#define WOFF_B2   98304
#define WOFF_R2   163840
#define WOFF_OUT  180224

// ---------------- tf32 split helpers ----------------
__device__ __forceinline__ void split_tf32(float x, uint32_t& hi, uint32_t& lo) {
    uint32_t xb = __float_as_uint(x) & 0xFFFFE000u;
    hi = xb;
    float l = x - __uint_as_float(xb);
    asm("cvt.rna.tf32.f32 %0, %1;" : "=r"(lo) : "f"(l));
}
__device__ __forceinline__ void mma8(float* d, const uint32_t* a, uint32_t b0, uint32_t b1) {
    asm volatile(
        "mma.sync.aligned.m16n8k8.row.col.f32.tf32.tf32.f32 "
        "{%0,%1,%2,%3}, {%4,%5,%6,%7}, {%8,%9}, {%0,%1,%2,%3};"
        : "+f"(d[0]), "+f"(d[1]), "+f"(d[2]), "+f"(d[3])
        : "r"(a[0]), "r"(a[1]), "r"(a[2]), "r"(a[3]), "r"(b0), "r"(b1));
}

// ---------------- cp.async helpers ----------------
__device__ __forceinline__ void cp16(uint32_t dst, const void* src, int srcsz) {
    asm volatile("cp.async.ca.shared.global [%0], [%1], 16, %2;"
                 :: "r"(dst), "l"(src), "r"(srcsz));
}
__device__ __forceinline__ void cp_commit() {
    asm volatile("cp.async.commit_group;");
}
template <int N>
__device__ __forceinline__ void cp_wait() {
    asm volatile("cp.async.wait_group %0;" :: "n"(N));
}

// ---------------- merged weight pre-split (6 matrices, one launch) ----------------
__global__ void splitW6_k(const float* W0, const float* W1, const float* W2,
                          const float* W3, const float* W4, const float* W5,
                          float* __restrict__ Wi) {
    int i = blockIdx.x * 256 + threadIdx.x;   // global element id, total 188416
    if (i >= 188416) return;
    const float* W; int local;
    if (i < 16384)        { W = W0; local = i; }
    else if (i < 81920)   { W = W1; local = i - 16384; }
    else if (i < 98304)   { W = W2; local = i - 81920; }
    else if (i < 163840)  { W = W3; local = i - 98304; }
    else if (i < 180224)  { W = W4; local = i - 163840; }
    else                  { W = W5; local = i - 180224; }
    uint32_t hi, lo;
    split_tf32(W[local], hi, lo);
    Wi[2 * i]     = __uint_as_float(hi);
    Wi[2 * i + 1] = __uint_as_float(lo);
}

// ---------------- sorting: histogram / 3-phase scan / scatter ----------------
__global__ void hist_k(const int* __restrict__ src, const int* __restrict__ dst,
                       const int* __restrict__ et,
                       int* __restrict__ hs, int* __restrict__ hd,
                       int* __restrict__ cq) {
    int e = blockIdx.x * 256 + threadIdx.x;
    if (e < EE) {
        int t = dst[e];
        atomicAdd(&hd[t], 1);
        atomicAdd(&hs[src[e]], 1);
        atomicAdd(&cq[t * RREL + et[e]], 1);
    }
}

// phase 1: per-block exclusive scan of 1024-chunk; partial = block total
__global__ void scan1_k(const int* __restrict__ h0, int* __restrict__ o0,
                        const int* __restrict__ h1, int* __restrict__ o1,
                        int* __restrict__ part) {
    int seg = blockIdx.y;
    const int* hist = seg ? h1 : h0;
    int* off        = seg ? o1 : o0;
    __shared__ int buf[2][1024];
    int t = threadIdx.x;
    int base = blockIdx.x * 1024;
    int v = (base + t < NN) ? hist[base + t] : 0;
    buf[0][t] = v;
    __syncthreads();
    int pi = 0;
#pragma unroll
    for (int ofs = 1; ofs < 1024; ofs <<= 1) {
        int x = buf[pi][t];
        if (t >= ofs) x += buf[pi][t - ofs];
        buf[pi ^ 1][t] = x;
        pi ^= 1;
        __syncthreads();
    }
    int incl = buf[pi][t];
    if (base + t < NN) off[base + t] = incl - v;      // block-local exclusive
    if (t == 1023) part[seg * 128 + blockIdx.x] = incl;
}

// phase 2: exclusive scan of the 98 partials per segment (one block, 256 thr)
__global__ void scan2_k(int* __restrict__ part) {
    __shared__ int b[2][2][128];
    int t = threadIdx.x;          // 0..255
    int seg = t >> 7, i = t & 127;
    int v = (i < 98) ? part[seg * 128 + i] : 0;
    b[0][seg][i] = v;
    __syncthreads();
    int pi = 0;
#pragma unroll
    for (int ofs = 1; ofs < 128; ofs <<= 1) {
        int x = b[pi][seg][i];
        if (i >= ofs) x += b[pi][seg][i - ofs];
        b[pi ^ 1][seg][i] = x;
        pi ^= 1;
        __syncthreads();
    }
    part[seg * 128 + i] = b[pi][seg][i] - v;          // exclusive
}

// phase 3: add partials, mirror into cur arrays. Total is EE by construction.
__global__ void scan3_k(int* __restrict__ o0, int* __restrict__ c0,
                        int* __restrict__ o1, int* __restrict__ c1,
                        const int* __restrict__ part) {
    int seg = blockIdx.y;
    int* off = seg ? o1 : o0;
    int* cur = seg ? c1 : c0;
    int i = blockIdx.x * 1024 + threadIdx.x;
    if (i < NN) {
        int o = off[i] + part[seg * 128 + blockIdx.x];
        off[i] = o;
        cur[i] = o;
    }
    if (i == 0) off[NN] = EE;
}

__global__ void scatter_k(const int* __restrict__ src, const int* __restrict__ dst,
                          const int* __restrict__ et,
                          int* __restrict__ curd, int* __restrict__ curs,
                          int* __restrict__ sd, int* __restrict__ ss) {
    int e = blockIdx.x * 256 + threadIdx.x;
    if (e < EE) {
        int s = src[e], t = dst[e], q = et[e];
        int p = atomicAdd(&curd[t], 1);
        sd[p] = s | (q << 20);
        int p2 = atomicAdd(&curs[s], 1);
        ss[p2] = t;
    }
}

// ---------------- passA body: register-accumulated fused mean+contraction -> Z ----------------
__device__ __forceinline__
void passA_body(int t, int d,
                const float* __restrict__ h, const float* __restrict__ comp,
                const int* __restrict__ offd, const int* __restrict__ sd,
                const int* __restrict__ cntq, float* __restrict__ Z,
                float* scoef, int* sed) {
    if (d < RREL * BBAS) {
        int q = d >> 2;
        float w = 1.0f / fmaxf((float)cntq[t * RREL + q], 1.0f);
        scoef[d] = comp[d] * w;
    }
    __syncthreads();

    float a0 = 0.f, a1 = 0.f, a2 = 0.f, a3 = 0.f;
    int e0 = offd[t], e1 = offd[t + 1];
    for (int base = e0; base < e1; base += 128) {
        int m = min(128, e1 - base);
        if (d < m) sed[d] = sd[base + d];
        __syncthreads();
        int i = 0;
        for (; i + 3 < m; i += 4) {
            int v0 = sed[i], v1 = sed[i + 1], v2 = sed[i + 2], v3 = sed[i + 3];
            float h0 = h[(size_t)(v0 & 0xFFFFF) * DDIM + d];
            float h1 = h[(size_t)(v1 & 0xFFFFF) * DDIM + d];
            float h2 = h[(size_t)(v2 & 0xFFFFF) * DDIM + d];
            float h3 = h[(size_t)(v3 & 0xFFFFF) * DDIM + d];
            float4 c0 = *(const float4*)(&scoef[(v0 >> 20) * 4]);
            float4 c1 = *(const float4*)(&scoef[(v1 >> 20) * 4]);
            float4 c2 = *(const float4*)(&scoef[(v2 >> 20) * 4]);
            float4 c3 = *(const float4*)(&scoef[(v3 >> 20) * 4]);
            a0 += c0.x * h0 + c1.x * h1 + c2.x * h2 + c3.x * h3;
            a1 += c0.y * h0 + c1.y * h1 + c2.y * h2 + c3.y * h3;
            a2 += c0.z * h0 + c1.z * h1 + c2.z * h2 + c3.z * h3;
            a3 += c0.w * h0 + c1.w * h1 + c2.w * h2 + c3.w * h3;
        }
        for (; i < m; ++i) {
            int v = sed[i];
            float hv = h[(size_t)(v & 0xFFFFF) * DDIM + d];
            float4 c = *(const float4*)(&scoef[(v >> 20) * 4]);
            a0 += c.x * hv;
            a1 += c.y * hv;
            a2 += c.z * hv;
            a3 += c.w * hv;
        }
        __syncthreads();
    }

    float* zr = Z + (size_t)t * 512;
    zr[0 * DDIM + d] = a0;
    zr[1 * DDIM + d] = a1;
    zr[2 * DDIM + d] = a2;
    zr[3 * DDIM + d] = a3;
}

// ---------------- passB body: per-src gate tau = tanh(mean |h_s - h_d|^2) ----------------
__device__ __forceinline__
void passB_body(int s, int d,
                const float* __restrict__ h, const int* __restrict__ offs,
                const int* __restrict__ ss, float* __restrict__ tau,
                int* sed) {
    int e0 = offs[s], e1 = offs[s + 1];
    float hs = h[(size_t)s * DDIM + d];
    float a0 = 0.f, a1 = 0.f, a2 = 0.f, a3 = 0.f;
    for (int base = e0; base < e1; base += 128) {
        int m = min(128, e1 - base);
        if (d < m) sed[d] = ss[base + d];
        __syncthreads();
        int i = 0;
        for (; i + 3 < m; i += 4) {
            float v0 = h[(size_t)sed[i + 0] * DDIM + d];
            float v1 = h[(size_t)sed[i + 1] * DDIM + d];
            float v2 = h[(size_t)sed[i + 2] * DDIM + d];
            float v3 = h[(size_t)sed[i + 3] * DDIM + d];
            float d0 = hs - v0, d1 = hs - v1, d2 = hs - v2, d3 = hs - v3;
            a0 += d0 * d0; a1 += d1 * d1; a2 += d2 * d2; a3 += d3 * d3;
        }
        for (; i < m; ++i) {
            float v = h[(size_t)sed[i] * DDIM + d];
            float df = hs - v;
            a0 += df * df;
        }
        __syncthreads();
    }
    float acc = (a0 + a1) + (a2 + a3);
    float ig = 1.0f / fmaxf((float)(e1 - e0), 1.0f);
    tau[(size_t)s * DDIM + d] = tanhf(acc * ig);
}

// ---------------- fused passA+passB: grid 2*NN, first half A, second half B ----------------
__global__ __launch_bounds__(128)
void passAB_k(const float* __restrict__ h, const float* __restrict__ comp,
              const int* __restrict__ offd, const int* __restrict__ sd,
              const int* __restrict__ cntq, float* __restrict__ Z,
              const int* __restrict__ offs, const int* __restrict__ ss,
              float* __restrict__ tau) {
    __shared__ float scoef[RREL * BBAS];
    __shared__ int   sed[128];
    int b = blockIdx.x;
    int d = threadIdx.x;
    if (b < NN) {
        passA_body(b, d, h, comp, offd, sd, cntq, Z, scoef, sed);
    } else {
        passB_body(b - NN, d, h, offs, ss, tau, sed);
    }
}

// ---------------- 3xTF32 MMA GEMM, cp.async double-buffered, BM=64, BK=16 ----------------
// C[M,NC] = epi( A[M,K] @ W ), A split at col K1A (A1/A2); W interleaved (hi,lo) [K][2*NC]
// 128 threads, warps 2x2.
template <int NC, int EPI>
__global__ __launch_bounds__(128)
void gemm_mma(const float* __restrict__ A1, int lda1, int K1A,
              const float* __restrict__ A2, int lda2,
              int M, int K,
              const float* __restrict__ Wi,
              const float* __restrict__ bias,
              const float* __restrict__ hprev,
              const float* __restrict__ tau,
              float* __restrict__ out) {
    constexpr int NCH   = NC / 2;         // cols per warp
    constexpr int NT    = NCH / 8;        // n8 tiles per warp
    constexpr int APAD  = 20;             // 16 + 4
    constexpr int BPAD2 = 2 * NC + 8;     // interleaved row stride
    __shared__ float As[2][64][APAD];
    __shared__ float Bs[2][16][BPAD2];

    const int tid  = threadIdx.x;
    const int lane = tid & 31;
    const int warp = tid >> 5;
    const int wm   = warp & 1;
    const int wn   = warp >> 1;
    const int g    = lane >> 2;
    const int tig  = lane & 3;
    const int row0 = blockIdx.x * 64;

    float acc[2][NT][4];
#pragma unroll
    for (int mt = 0; mt < 2; ++mt)
#pragma unroll
        for (int nt = 0; nt < NT; ++nt)
#pragma unroll
            for (int j = 0; j < 4; ++j) acc[mt][nt][j] = 0.f;

    const int nch = K >> 4;

    auto load_chunk = [&](int c, int buf) {
        const int k0g = c << 4;
        const float* Ap; int lda;
        if (k0g < K1A) { Ap = A1 + k0g; lda = lda1; }
        else           { Ap = A2 + (k0g - K1A); lda = lda2; }
        // A: 64 rows x 4 float4 = 256 slots, 2/thread
#pragma unroll
        for (int u = 0; u < 2; ++u) {
            int f = u * 128 + tid;
            int r = f >> 2;
            int q = f & 3;
            int grow = row0 + r;
            uint32_t dsts = (uint32_t)__cvta_generic_to_shared(&As[buf][r][q * 4]);
            const float* srcp = Ap + (size_t)(grow < M ? grow : 0) * lda + q * 4;
            cp16(dsts, srcp, grow < M ? 16 : 0);
        }
        // B: 16 rows x (NC/2) float4
        const float* Wp = Wi + (size_t)k0g * (2 * NC);
#pragma unroll
        for (int u = 0; u < NC / 16; ++u) {
            int f = u * 128 + tid;
            int r = f / (NC / 2);
            int c4 = f % (NC / 2);
            uint32_t dsts = (uint32_t)__cvta_generic_to_shared(&Bs[buf][r][c4 * 4]);
            cp16(dsts, Wp + (size_t)r * 2 * NC + c4 * 4, 16);
        }
    };

    load_chunk(0, 0);
    cp_commit();

    for (int c = 0; c < nch; ++c) {
        const int buf = c & 1;
        if (c + 1 < nch) {
            load_chunk(c + 1, buf ^ 1);
            cp_commit();
            cp_wait<1>();
        } else {
            cp_wait<0>();
        }
        __syncthreads();

#pragma unroll
        for (int k8 = 0; k8 < 2; ++k8) {
            const int k0 = k8 * 8;
            uint32_t ah[2][4], al[2][4];
#pragma unroll
            for (int mt = 0; mt < 2; ++mt) {
                int rb = wm * 32 + mt * 16 + g;
                split_tf32(As[buf][rb][k0 + tig],          ah[mt][0], al[mt][0]);
                split_tf32(As[buf][rb + 8][k0 + tig],      ah[mt][1], al[mt][1]);
                split_tf32(As[buf][rb][k0 + tig + 4],      ah[mt][2], al[mt][2]);
                split_tf32(As[buf][rb + 8][k0 + tig + 4],  ah[mt][3], al[mt][3]);
            }
#pragma unroll
            for (int nt = 0; nt < NT; ++nt) {
                int cb = wn * NCH + nt * 8 + g;
                float2 p0 = *(const float2*)(&Bs[buf][k0 + tig][2 * cb]);
                float2 p1 = *(const float2*)(&Bs[buf][k0 + tig + 4][2 * cb]);
                uint32_t bh0 = __float_as_uint(p0.x), bl0 = __float_as_uint(p0.y);
                uint32_t bh1 = __float_as_uint(p1.x), bl1 = __float_as_uint(p1.y);
#pragma unroll
                for (int mt = 0; mt < 2; ++mt) {
                    mma8(acc[mt][nt], ah[mt], bh0, bh1);
                    mma8(acc[mt][nt], al[mt], bh0, bh1);
                    mma8(acc[mt][nt], ah[mt], bl0, bl1);
                }
            }
        }
        __syncthreads();
    }

    // ---- epilogue ----
#pragma unroll
    for (int mt = 0; mt < 2; ++mt) {
#pragma unroll
        for (int nt = 0; nt < NT; ++nt) {
            int col = wn * NCH + nt * 8 + 2 * tig;
            int r0 = row0 + wm * 32 + mt * 16 + g;
#pragma unroll
            for (int half = 0; half < 2; ++half) {
                int row = r0 + half * 8;
                if (row >= M) continue;
                float c0 = acc[mt][nt][half * 2 + 0];
                float c1 = acc[mt][nt][half * 2 + 1];
                if (EPI == 0) {
                    c0 = fmaxf(c0 + bias[col], 0.f);
                    c1 = fmaxf(c1 + bias[col + 1], 0.f);
                } else if (EPI == 1) {
                    float hn0 = fmaxf(c0 + bias[col], 0.f);
                    float hn1 = fmaxf(c1 + bias[col + 1], 0.f);
                    float hp0 = hprev[(size_t)row * DDIM + col];
                    float hp1 = hprev[(size_t)row * DDIM + col + 1];
                    float t0 = tau[(size_t)row * DDIM + col];
                    float t1 = tau[(size_t)row * DDIM + col + 1];
                    c0 = hp0 + t0 * (hn0 - hp0);
                    c1 = hp1 + t1 * (hn1 - hp1);
                } else {
                    c0 += bias[col];
                    c1 += bias[col + 1];
                }
                *(float2*)(out + (size_t)row * NC + col) = make_float2(c0, c1);
            }
        }
    }
}

// ---------------- launch ----------------
extern "C" void kernel_launch(void* const* d_in, const int* in_sizes, int n_in,
                              void* d_out, int out_size) {
    (void)in_sizes; (void)n_in; (void)out_size;
    const float* x      = (const float*)d_in[0];
    const int*   src    = (const int*)d_in[1];
    const int*   dst    = (const int*)d_in[2];
    const int*   et     = (const int*)d_in[3];
    const float* projW  = (const float*)d_in[4];
    const float* projb  = (const float*)d_in[5];
    const float* basis1 = (const float*)d_in[6];
    const float* comp1  = (const float*)d_in[7];
    const float* root1  = (const float*)d_in[8];
    const float* bias1  = (const float*)d_in[9];
    const float* basis2 = (const float*)d_in[10];
    const float* comp2  = (const float*)d_in[11];
    const float* root2  = (const float*)d_in[12];
    const float* bias2  = (const float*)d_in[13];
    const float* outW   = (const float*)d_in[14];
    const float* outb   = (const float*)d_in[15];

    float* o  = (float*)d_out;
    float* L0 = o + (size_t)NN * OUTD;        // latents[0]
    float* L1 = L0 + (size_t)NN * DDIM;       // latents[1]
    float* L2 = L1 + (size_t)NN * DDIM;       // latents[2]

    float *Z, *tau, *Wi;
    int *sd, *ss, *offd, *offs, *curd, *curs, *cntq, *part;
    cudaGetSymbolAddress((void**)&Z,    g_Z);
    cudaGetSymbolAddress((void**)&tau,  g_tau);
    cudaGetSymbolAddress((void**)&Wi,   g_Wi);
    cudaGetSymbolAddress((void**)&sd,   g_sd);
    cudaGetSymbolAddress((void**)&ss,   g_ss);
    cudaGetSymbolAddress((void**)&offd, g_offd);
    cudaGetSymbolAddress((void**)&offs, g_offs);
    cudaGetSymbolAddress((void**)&curd, g_curd);
    cudaGetSymbolAddress((void**)&curs, g_curs);
    cudaGetSymbolAddress((void**)&cntq, g_cntq);
    cudaGetSymbolAddress((void**)&part, g_part);

    const int gblocks = (NN + 63) / 64;       // 1563
    const int eblocks = (EE + 255) / 256;
    const int nblk1k  = (NN + 1023) / 1024;   // 98

    // ---- pre-split weights (layer-invariant, one launch) ----
    splitW6_k<<<(188416 + 255) / 256, 256>>>(projW, basis1, root1, basis2, root2, outW, Wi);

    // ---- build CSR + per-(dst,rel) counts (layer-invariant) ----
    cudaMemsetAsync(curd, 0, NN * sizeof(int));
    cudaMemsetAsync(curs, 0, NN * sizeof(int));
    cudaMemsetAsync(cntq, 0, NN * RREL * sizeof(int));
    hist_k<<<eblocks, 256>>>(src, dst, et, curs, curd, cntq);
    scan1_k<<<dim3(nblk1k, 2), 1024>>>(curd, offd, curs, offs, part);
    scan2_k<<<1, 256>>>(part);
    scan3_k<<<dim3(nblk1k, 2), 1024>>>(offd, curd, offs, curs, part);
    scatter_k<<<eblocks, 256>>>(src, dst, et, curd, curs, sd, ss);

    // ---- input projection: h0 = relu(x @ projW + projb) ----
    gemm_mma<128, 0><<<gblocks, 128>>>(x, 128, 128, x, 128, NN, 128,
                                       Wi + 2 * WOFF_PROJ,
                                       projb, nullptr, nullptr, L0);

    // ---- layer 1 ----
    passAB_k<<<2 * NN, 128>>>(L0, comp1, offd, sd, cntq, Z, offs, ss, tau);
    gemm_mma<128, 1><<<gblocks, 128>>>(Z, 512, 512, L0, 128, NN, 640,
                                       Wi + 2 * WOFF_B1,
                                       bias1, L0, tau, L1);

    // ---- layer 2 ----
    passAB_k<<<2 * NN, 128>>>(L1, comp2, offd, sd, cntq, Z, offs, ss, tau);
    gemm_mma<128, 1><<<gblocks, 128>>>(Z, 512, 512, L1, 128, NN, 640,
                                       Wi + 2 * WOFF_B2,
                                       bias2, L1, tau, L2);

    // ---- final: out = h2 @ outW + outb ----
    gemm_mma<64, 2><<<gblocks, 128>>>(L2, 128, 128, L2, 128, NN, 128,
                                      Wi + 2 * WOFF_OUT,
                                      outb, nullptr, nullptr, o);
}

// round 16
// speedup vs baseline: 1.1389x; 1.0033x over previous
#include <cuda_runtime.h>
#include <cstdint>
#include <cstddef>

#define NN   100000
#define EE   1600000
#define DDIM 128
#define RREL 8
#define BBAS 4
#define OUTD 64

// ---------------- scratch (no cudaMalloc allowed) ----------------
__device__ float g_Z[(size_t)NN * 512];     // contracted aggregate [N, B*D]
__device__ float g_tau[(size_t)NN * DDIM];  // gate tau [N, D]
__device__ int   g_sd[EE];                  // edges sorted by dst: src | (q<<20)
__device__ int   g_ss[EE];                  // edges sorted by src: dst
__device__ int   g_offd[NN + 1];
__device__ int   g_offs[NN + 1];
__device__ int   g_curd[NN];
__device__ int   g_curs[NN];
__device__ int   g_cntq[NN * RREL];         // per-(dst,rel) edge counts
__device__ int   g_part[2 * 128];           // scan partials (raw block totals)
// interleaved tf32 (hi,lo) weights: proj | basis1,root1 | basis2,root2 | outW
__device__ float g_Wi[2 * 188416];

#define WOFF_PROJ 0
#define WOFF_B1   16384
#define WOFF_R1   81920
#define WOFF_B2   98304
#define WOFF_R2   163840
#define WOFF_OUT  180224

// ---------------- tf32 split helpers ----------------
__device__ __forceinline__ void split_tf32(float x, uint32_t& hi, uint32_t& lo) {
    uint32_t xb = __float_as_uint(x) & 0xFFFFE000u;
    hi = xb;
    float l = x - __uint_as_float(xb);
    asm("cvt.rna.tf32.f32 %0, %1;" : "=r"(lo) : "f"(l));
}
__device__ __forceinline__ void mma8(float* d, const uint32_t* a, uint32_t b0, uint32_t b1) {
    asm volatile(
        "mma.sync.aligned.m16n8k8.row.col.f32.tf32.tf32.f32 "
        "{%0,%1,%2,%3}, {%4,%5,%6,%7}, {%8,%9}, {%0,%1,%2,%3};"
        : "+f"(d[0]), "+f"(d[1]), "+f"(d[2]), "+f"(d[3])
        : "r"(a[0]), "r"(a[1]), "r"(a[2]), "r"(a[3]), "r"(b0), "r"(b1));
}

// ---------------- cp.async helpers ----------------
__device__ __forceinline__ void cp16(uint32_t dst, const void* src, int srcsz) {
    asm volatile("cp.async.ca.shared.global [%0], [%1], 16, %2;"
                 :: "r"(dst), "l"(src), "r"(srcsz));
}
__device__ __forceinline__ void cp_commit() {
    asm volatile("cp.async.commit_group;");
}
template <int N>
__device__ __forceinline__ void cp_wait() {
    asm volatile("cp.async.wait_group %0;" :: "n"(N));
}

// ---------------- zero all count arrays in one launch ----------------
__global__ void zero3_k(int* __restrict__ curd, int* __restrict__ curs,
                        int* __restrict__ cntq) {
    int i = blockIdx.x * 256 + threadIdx.x;
    if (i < NN) { curd[i] = 0; curs[i] = 0; }
    if (i < NN * RREL) cntq[i] = 0;
}

// ---------------- combined histogram + weight pre-split (one launch) ----------------
// blocks [0, EB): edge histogram; blocks [EB, EB+WB): tf32 weight split.
#define HIST_EB ((EE + 255) / 256)
#define SPLIT_WB ((188416 + 255) / 256)
__global__ void histsplit_k(const int* __restrict__ src, const int* __restrict__ dst,
                            const int* __restrict__ et,
                            int* __restrict__ hs, int* __restrict__ hd,
                            int* __restrict__ cq,
                            const float* W0, const float* W1, const float* W2,
                            const float* W3, const float* W4, const float* W5,
                            float* __restrict__ Wi) {
    if (blockIdx.x < HIST_EB) {
        int e = blockIdx.x * 256 + threadIdx.x;
        if (e < EE) {
            int t = dst[e];
            atomicAdd(&hd[t], 1);
            atomicAdd(&hs[src[e]], 1);
            atomicAdd(&cq[t * RREL + et[e]], 1);
        }
    } else {
        int i = (blockIdx.x - HIST_EB) * 256 + threadIdx.x;
        if (i >= 188416) return;
        const float* W; int local;
        if (i < 16384)        { W = W0; local = i; }
        else if (i < 81920)   { W = W1; local = i - 16384; }
        else if (i < 98304)   { W = W2; local = i - 81920; }
        else if (i < 163840)  { W = W3; local = i - 98304; }
        else if (i < 180224)  { W = W4; local = i - 163840; }
        else                  { W = W5; local = i - 180224; }
        uint32_t hi, lo;
        split_tf32(W[local], hi, lo);
        Wi[2 * i]     = __uint_as_float(hi);
        Wi[2 * i + 1] = __uint_as_float(lo);
    }
}

// ---------------- scan phase 1: per-block exclusive scan; part = RAW block total ----------------
__global__ void scan1_k(const int* __restrict__ h0, int* __restrict__ o0,
                        const int* __restrict__ h1, int* __restrict__ o1,
                        int* __restrict__ part) {
    int seg = blockIdx.y;
    const int* hist = seg ? h1 : h0;
    int* off        = seg ? o1 : o0;
    __shared__ int buf[2][1024];
    int t = threadIdx.x;
    int base = blockIdx.x * 1024;
    int v = (base + t < NN) ? hist[base + t] : 0;
    buf[0][t] = v;
    __syncthreads();
    int pi = 0;
#pragma unroll
    for (int ofs = 1; ofs < 1024; ofs <<= 1) {
        int x = buf[pi][t];
        if (t >= ofs) x += buf[pi][t - ofs];
        buf[pi ^ 1][t] = x;
        pi ^= 1;
        __syncthreads();
    }
    int incl = buf[pi][t];
    if (base + t < NN) off[base + t] = incl - v;      // block-local exclusive
    if (t == 1023) part[seg * 128 + blockIdx.x] = incl;
}

// ---------------- scan phase 2 (folded): each block derives its own base from raw partials ----
__global__ void scan3_k(int* __restrict__ o0, int* __restrict__ c0,
                        int* __restrict__ o1, int* __restrict__ c1,
                        const int* __restrict__ part) {
    int seg = blockIdx.y;
    int* off = seg ? o1 : o0;
    int* cur = seg ? c1 : c0;
    __shared__ int sp[128];
    int t = threadIdx.x;
    int bx = blockIdx.x;
    if (t < 128) sp[t] = (t < bx && t < 98) ? part[seg * 128 + t] : 0;
    __syncthreads();
    // tree-reduce 128 -> 1 (threads < 64 active per step)
#pragma unroll
    for (int ofs = 64; ofs > 0; ofs >>= 1) {
        if (t < ofs) sp[t] += sp[t + ofs];
        __syncthreads();
    }
    int basev = sp[0];
    int i = bx * 1024 + t;
    if (i < NN) {
        int o = off[i] + basev;
        off[i] = o;
        cur[i] = o;
    }
    if (i == 0) off[NN] = EE;
}

__global__ void scatter_k(const int* __restrict__ src, const int* __restrict__ dst,
                          const int* __restrict__ et,
                          int* __restrict__ curd, int* __restrict__ curs,
                          int* __restrict__ sd, int* __restrict__ ss) {
    int e = blockIdx.x * 256 + threadIdx.x;
    if (e < EE) {
        int s = src[e], t = dst[e], q = et[e];
        int p = atomicAdd(&curd[t], 1);
        sd[p] = s | (q << 20);
        int p2 = atomicAdd(&curs[s], 1);
        ss[p2] = t;
    }
}

// ---------------- passA body: register-accumulated fused mean+contraction -> Z ----------------
__device__ __forceinline__
void passA_body(int t, int d,
                const float* __restrict__ h, const float* __restrict__ comp,
                const int* __restrict__ offd, const int* __restrict__ sd,
                const int* __restrict__ cntq, float* __restrict__ Z,
                float* scoef, int* sed) {
    if (d < RREL * BBAS) {
        int q = d >> 2;
        float w = 1.0f / fmaxf((float)cntq[t * RREL + q], 1.0f);
        scoef[d] = comp[d] * w;
    }
    __syncthreads();

    float a0 = 0.f, a1 = 0.f, a2 = 0.f, a3 = 0.f;
    int e0 = offd[t], e1 = offd[t + 1];
    for (int base = e0; base < e1; base += 128) {
        int m = min(128, e1 - base);
        if (d < m) sed[d] = sd[base + d];
        __syncthreads();
        int i = 0;
        for (; i + 3 < m; i += 4) {
            int v0 = sed[i], v1 = sed[i + 1], v2 = sed[i + 2], v3 = sed[i + 3];
            float h0 = h[(size_t)(v0 & 0xFFFFF) * DDIM + d];
            float h1 = h[(size_t)(v1 & 0xFFFFF) * DDIM + d];
            float h2 = h[(size_t)(v2 & 0xFFFFF) * DDIM + d];
            float h3 = h[(size_t)(v3 & 0xFFFFF) * DDIM + d];
            float4 c0 = *(const float4*)(&scoef[(v0 >> 20) * 4]);
            float4 c1 = *(const float4*)(&scoef[(v1 >> 20) * 4]);
            float4 c2 = *(const float4*)(&scoef[(v2 >> 20) * 4]);
            float4 c3 = *(const float4*)(&scoef[(v3 >> 20) * 4]);
            a0 += c0.x * h0 + c1.x * h1 + c2.x * h2 + c3.x * h3;
            a1 += c0.y * h0 + c1.y * h1 + c2.y * h2 + c3.y * h3;
            a2 += c0.z * h0 + c1.z * h1 + c2.z * h2 + c3.z * h3;
            a3 += c0.w * h0 + c1.w * h1 + c2.w * h2 + c3.w * h3;
        }
        for (; i < m; ++i) {
            int v = sed[i];
            float hv = h[(size_t)(v & 0xFFFFF) * DDIM + d];
            float4 c = *(const float4*)(&scoef[(v >> 20) * 4]);
            a0 += c.x * hv;
            a1 += c.y * hv;
            a2 += c.z * hv;
            a3 += c.w * hv;
        }
        __syncthreads();
    }

    float* zr = Z + (size_t)t * 512;
    zr[0 * DDIM + d] = a0;
    zr[1 * DDIM + d] = a1;
    zr[2 * DDIM + d] = a2;
    zr[3 * DDIM + d] = a3;
}

// ---------------- passB body: per-src gate tau = tanh(mean |h_s - h_d|^2) ----------------
__device__ __forceinline__
void passB_body(int s, int d,
                const float* __restrict__ h, const int* __restrict__ offs,
                const int* __restrict__ ss, float* __restrict__ tau,
                int* sed) {
    int e0 = offs[s], e1 = offs[s + 1];
    float hs = h[(size_t)s * DDIM + d];
    float a0 = 0.f, a1 = 0.f, a2 = 0.f, a3 = 0.f;
    for (int base = e0; base < e1; base += 128) {
        int m = min(128, e1 - base);
        if (d < m) sed[d] = ss[base + d];
        __syncthreads();
        int i = 0;
        for (; i + 3 < m; i += 4) {
            float v0 = h[(size_t)sed[i + 0] * DDIM + d];
            float v1 = h[(size_t)sed[i + 1] * DDIM + d];
            float v2 = h[(size_t)sed[i + 2] * DDIM + d];
            float v3 = h[(size_t)sed[i + 3] * DDIM + d];
            float d0 = hs - v0, d1 = hs - v1, d2 = hs - v2, d3 = hs - v3;
            a0 += d0 * d0; a1 += d1 * d1; a2 += d2 * d2; a3 += d3 * d3;
        }
        for (; i < m; ++i) {
            float v = h[(size_t)sed[i] * DDIM + d];
            float df = hs - v;
            a0 += df * df;
        }
        __syncthreads();
    }
    float acc = (a0 + a1) + (a2 + a3);
    float ig = 1.0f / fmaxf((float)(e1 - e0), 1.0f);
    tau[(size_t)s * DDIM + d] = tanhf(acc * ig);
}

// ---------------- fused passA+passB: grid 2*NN, first half A, second half B ----------------
__global__ __launch_bounds__(128)
void passAB_k(const float* __restrict__ h, const float* __restrict__ comp,
              const int* __restrict__ offd, const int* __restrict__ sd,
              const int* __restrict__ cntq, float* __restrict__ Z,
              const int* __restrict__ offs, const int* __restrict__ ss,
              float* __restrict__ tau) {
    __shared__ float scoef[RREL * BBAS];
    __shared__ int   sed[128];
    int b = blockIdx.x;
    int d = threadIdx.x;
    if (b < NN) {
        passA_body(b, d, h, comp, offd, sd, cntq, Z, scoef, sed);
    } else {
        passB_body(b - NN, d, h, offs, ss, tau, sed);
    }
}

// ---------------- 3xTF32 MMA GEMM, cp.async double-buffered, BM=64, BK=16 ----------------
// C[M,NC] = epi( A[M,K] @ W ), A split at col K1A (A1/A2); W interleaved (hi,lo) [K][2*NC]
// 128 threads, warps 2x2.
template <int NC, int EPI>
__global__ __launch_bounds__(128)
void gemm_mma(const float* __restrict__ A1, int lda1, int K1A,
              const float* __restrict__ A2, int lda2,
              int M, int K,
              const float* __restrict__ Wi,
              const float* __restrict__ bias,
              const float* __restrict__ hprev,
              const float* __restrict__ tau,
              float* __restrict__ out) {
    constexpr int NCH   = NC / 2;         // cols per warp
    constexpr int NT    = NCH / 8;        // n8 tiles per warp
    constexpr int APAD  = 20;             // 16 + 4
    constexpr int BPAD2 = 2 * NC + 8;     // interleaved row stride
    __shared__ float As[2][64][APAD];
    __shared__ float Bs[2][16][BPAD2];

    const int tid  = threadIdx.x;
    const int lane = tid & 31;
    const int warp = tid >> 5;
    const int wm   = warp & 1;
    const int wn   = warp >> 1;
    const int g    = lane >> 2;
    const int tig  = lane & 3;
    const int row0 = blockIdx.x * 64;

    float acc[2][NT][4];
#pragma unroll
    for (int mt = 0; mt < 2; ++mt)
#pragma unroll
        for (int nt = 0; nt < NT; ++nt)
#pragma unroll
            for (int j = 0; j < 4; ++j) acc[mt][nt][j] = 0.f;

    const int nch = K >> 4;

    auto load_chunk = [&](int c, int buf) {
        const int k0g = c << 4;
        const float* Ap; int lda;
        if (k0g < K1A) { Ap = A1 + k0g; lda = lda1; }
        else           { Ap = A2 + (k0g - K1A); lda = lda2; }
        // A: 64 rows x 4 float4 = 256 slots, 2/thread
#pragma unroll
        for (int u = 0; u < 2; ++u) {
            int f = u * 128 + tid;
            int r = f >> 2;
            int q = f & 3;
            int grow = row0 + r;
            uint32_t dsts = (uint32_t)__cvta_generic_to_shared(&As[buf][r][q * 4]);
            const float* srcp = Ap + (size_t)(grow < M ? grow : 0) * lda + q * 4;
            cp16(dsts, srcp, grow < M ? 16 : 0);
        }
        // B: 16 rows x (NC/2) float4
        const float* Wp = Wi + (size_t)k0g * (2 * NC);
#pragma unroll
        for (int u = 0; u < NC / 16; ++u) {
            int f = u * 128 + tid;
            int r = f / (NC / 2);
            int c4 = f % (NC / 2);
            uint32_t dsts = (uint32_t)__cvta_generic_to_shared(&Bs[buf][r][c4 * 4]);
            cp16(dsts, Wp + (size_t)r * 2 * NC + c4 * 4, 16);
        }
    };

    load_chunk(0, 0);
    cp_commit();

    for (int c = 0; c < nch; ++c) {
        const int buf = c & 1;
        if (c + 1 < nch) {
            load_chunk(c + 1, buf ^ 1);
            cp_commit();
            cp_wait<1>();
        } else {
            cp_wait<0>();
        }
        __syncthreads();

#pragma unroll
        for (int k8 = 0; k8 < 2; ++k8) {
            const int k0 = k8 * 8;
            uint32_t ah[2][4], al[2][4];
#pragma unroll
            for (int mt = 0; mt < 2; ++mt) {
                int rb = wm * 32 + mt * 16 + g;
                split_tf32(As[buf][rb][k0 + tig],          ah[mt][0], al[mt][0]);
                split_tf32(As[buf][rb + 8][k0 + tig],      ah[mt][1], al[mt][1]);
                split_tf32(As[buf][rb][k0 + tig + 4],      ah[mt][2], al[mt][2]);
                split_tf32(As[buf][rb + 8][k0 + tig + 4],  ah[mt][3], al[mt][3]);
            }
#pragma unroll
            for (int nt = 0; nt < NT; ++nt) {
                int cb = wn * NCH + nt * 8 + g;
                float2 p0 = *(const float2*)(&Bs[buf][k0 + tig][2 * cb]);
                float2 p1 = *(const float2*)(&Bs[buf][k0 + tig + 4][2 * cb]);
                uint32_t bh0 = __float_as_uint(p0.x), bl0 = __float_as_uint(p0.y);
                uint32_t bh1 = __float_as_uint(p1.x), bl1 = __float_as_uint(p1.y);
#pragma unroll
                for (int mt = 0; mt < 2; ++mt) {
                    mma8(acc[mt][nt], ah[mt], bh0, bh1);
                    mma8(acc[mt][nt], al[mt], bh0, bh1);
                    mma8(acc[mt][nt], ah[mt], bl0, bl1);
                }
            }
        }
        __syncthreads();
    }

    // ---- epilogue ----
#pragma unroll
    for (int mt = 0; mt < 2; ++mt) {
#pragma unroll
        for (int nt = 0; nt < NT; ++nt) {
            int col = wn * NCH + nt * 8 + 2 * tig;
            int r0 = row0 + wm * 32 + mt * 16 + g;
#pragma unroll
            for (int half = 0; half < 2; ++half) {
                int row = r0 + half * 8;
                if (row >= M) continue;
                float c0 = acc[mt][nt][half * 2 + 0];
                float c1 = acc[mt][nt][half * 2 + 1];
                if (EPI == 0) {
                    c0 = fmaxf(c0 + bias[col], 0.f);
                    c1 = fmaxf(c1 + bias[col + 1], 0.f);
                } else if (EPI == 1) {
                    float hn0 = fmaxf(c0 + bias[col], 0.f);
                    float hn1 = fmaxf(c1 + bias[col + 1], 0.f);
                    float hp0 = hprev[(size_t)row * DDIM + col];
                    float hp1 = hprev[(size_t)row * DDIM + col + 1];
                    float t0 = tau[(size_t)row * DDIM + col];
                    float t1 = tau[(size_t)row * DDIM + col + 1];
                    c0 = hp0 + t0 * (hn0 - hp0);
                    c1 = hp1 + t1 * (hn1 - hp1);
                } else {
                    c0 += bias[col];
                    c1 += bias[col + 1];
                }
                *(float2*)(out + (size_t)row * NC + col) = make_float2(c0, c1);
            }
        }
    }
}

// ---------------- launch ----------------
extern "C" void kernel_launch(void* const* d_in, const int* in_sizes, int n_in,
                              void* d_out, int out_size) {
    (void)in_sizes; (void)n_in; (void)out_size;
    const float* x      = (const float*)d_in[0];
    const int*   src    = (const int*)d_in[1];
    const int*   dst    = (const int*)d_in[2];
    const int*   et     = (const int*)d_in[3];
    const float* projW  = (const float*)d_in[4];
    const float* projb  = (const float*)d_in[5];
    const float* basis1 = (const float*)d_in[6];
    const float* comp1  = (const float*)d_in[7];
    const float* root1  = (const float*)d_in[8];
    const float* bias1  = (const float*)d_in[9];
    const float* basis2 = (const float*)d_in[10];
    const float* comp2  = (const float*)d_in[11];
    const float* root2  = (const float*)d_in[12];
    const float* bias2  = (const float*)d_in[13];
    const float* outW   = (const float*)d_in[14];
    const float* outb   = (const float*)d_in[15];

    float* o  = (float*)d_out;
    float* L0 = o + (size_t)NN * OUTD;        // latents[0]
    float* L1 = L0 + (size_t)NN * DDIM;       // latents[1]
    float* L2 = L1 + (size_t)NN * DDIM;       // latents[2]

    float *Z, *tau, *Wi;
    int *sd, *ss, *offd, *offs, *curd, *curs, *cntq, *part;
    cudaGetSymbolAddress((void**)&Z,    g_Z);
    cudaGetSymbolAddress((void**)&tau,  g_tau);
    cudaGetSymbolAddress((void**)&Wi,   g_Wi);
    cudaGetSymbolAddress((void**)&sd,   g_sd);
    cudaGetSymbolAddress((void**)&ss,   g_ss);
    cudaGetSymbolAddress((void**)&offd, g_offd);
    cudaGetSymbolAddress((void**)&offs, g_offs);
    cudaGetSymbolAddress((void**)&curd, g_curd);
    cudaGetSymbolAddress((void**)&curs, g_curs);
    cudaGetSymbolAddress((void**)&cntq, g_cntq);
    cudaGetSymbolAddress((void**)&part, g_part);

    const int gblocks = (NN + 63) / 64;       // 1563
    const int nblk1k  = (NN + 1023) / 1024;   // 98
    const int zblocks = (NN * RREL + 255) / 256;

    // ---- prep: zero counters, then combined histogram + weight split ----
    zero3_k<<<zblocks, 256>>>(curd, curs, cntq);
    histsplit_k<<<HIST_EB + SPLIT_WB, 256>>>(src, dst, et, curs, curd, cntq,
                                             projW, basis1, root1, basis2, root2, outW, Wi);
    scan1_k<<<dim3(nblk1k, 2), 1024>>>(curd, offd, curs, offs, part);
    scan3_k<<<dim3(nblk1k, 2), 1024>>>(offd, curd, offs, curs, part);
    scatter_k<<<HIST_EB, 256>>>(src, dst, et, curd, curs, sd, ss);

    // ---- input projection: h0 = relu(x @ projW + projb) ----
    gemm_mma<128, 0><<<gblocks, 128>>>(x, 128, 128, x, 128, NN, 128,
                                       Wi + 2 * WOFF_PROJ,
                                       projb, nullptr, nullptr, L0);

    // ---- layer 1 ----
    passAB_k<<<2 * NN, 128>>>(L0, comp1, offd, sd, cntq, Z, offs, ss, tau);
    gemm_mma<128, 1><<<gblocks, 128>>>(Z, 512, 512, L0, 128, NN, 640,
                                       Wi + 2 * WOFF_B1,
                                       bias1, L0, tau, L1);

    // ---- layer 2 ----
    passAB_k<<<2 * NN, 128>>>(L1, comp2, offd, sd, cntq, Z, offs, ss, tau);
    gemm_mma<128, 1><<<gblocks, 128>>>(Z, 512, 512, L1, 128, NN, 640,
                                       Wi + 2 * WOFF_B2,
                                       bias2, L1, tau, L2);

    // ---- final: out = h2 @ outW + outb ----
    gemm_mma<64, 2><<<gblocks, 128>>>(L2, 128, 128, L2, 128, NN, 128,
                                      Wi + 2 * WOFF_OUT,
                                      outb, nullptr, nullptr, o);
}